// round 1
// baseline (speedup 1.0000x reference)
#include <cuda_runtime.h>
#include <math.h>

#define B_    4
#define S_    1024
#define D_    4096
#define H_    32
#define HKV_  8
#define HD_   128
#define KVD_  (HKV_*HD_)   // 1024

// Scratch (static device globals; no runtime allocation)
__device__ float g_xq[B_*S_*D_];        // 64 MB
__device__ float g_xk[B_*S_*KVD_];      // 16 MB
__device__ float g_xv[B_*S_*KVD_];      // 16 MB
__device__ float g_attn[B_*S_*D_];      // 64 MB

// ---------------------------------------------------------------------------
// SGEMM: C[M,N] = A[M,K] @ B[K,N], all row-major, M%128==0, N%128==0, K%8==0
// 128x128 tile, BK=8, 256 threads, 8x8 per-thread microtile.
// ---------------------------------------------------------------------------
__global__ void __launch_bounds__(256) sgemm128(const float* __restrict__ A,
                                                const float* __restrict__ Bm,
                                                float* __restrict__ C,
                                                int M, int N, int K)
{
    __shared__ float As[8][132];   // padded: avoids store-bank conflicts
    __shared__ float Bs[8][128];

    const int tid = threadIdx.x;
    const int ty  = tid >> 4;      // 0..15
    const int tx  = tid & 15;      // 0..15
    const int rowBase = blockIdx.y * 128;
    const int colBase = blockIdx.x * 128;

    const int arow = tid >> 1;           // 0..127
    const int acol = (tid & 1) * 4;      // 0 or 4
    const int brow = tid >> 5;           // 0..7
    const int bcol = (tid & 31) * 4;     // 0..124

    const float* Arow = A  + (size_t)(rowBase + arow) * K + acol;
    const float* Bptr = Bm + (size_t)brow * N + colBase + bcol;

    float4 areg = *(const float4*)(Arow);
    float4 breg = *(const float4*)(Bptr);

    float acc[8][8];
    #pragma unroll
    for (int i = 0; i < 8; i++)
        #pragma unroll
        for (int j = 0; j < 8; j++) acc[i][j] = 0.f;

    for (int k0 = 0; k0 < K; k0 += 8) {
        // commit staged tile to smem
        As[acol + 0][arow] = areg.x;
        As[acol + 1][arow] = areg.y;
        As[acol + 2][arow] = areg.z;
        As[acol + 3][arow] = areg.w;
        *(float4*)&Bs[brow][bcol] = breg;
        __syncthreads();

        // prefetch next tile
        if (k0 + 8 < K) {
            areg = *(const float4*)(Arow + k0 + 8);
            breg = *(const float4*)(Bptr + (size_t)(k0 + 8) * N);
        }

        #pragma unroll
        for (int kk = 0; kk < 8; kk++) {
            float4 a0 = *(const float4*)&As[kk][ty * 8];
            float4 a1 = *(const float4*)&As[kk][ty * 8 + 4];
            float4 b0 = *(const float4*)&Bs[kk][tx * 8];
            float4 b1 = *(const float4*)&Bs[kk][tx * 8 + 4];
            float av[8] = {a0.x, a0.y, a0.z, a0.w, a1.x, a1.y, a1.z, a1.w};
            float bv[8] = {b0.x, b0.y, b0.z, b0.w, b1.x, b1.y, b1.z, b1.w};
            #pragma unroll
            for (int i = 0; i < 8; i++)
                #pragma unroll
                for (int j = 0; j < 8; j++)
                    acc[i][j] += av[i] * bv[j];
        }
        __syncthreads();
    }

    #pragma unroll
    for (int i = 0; i < 8; i++) {
        float* crow = C + (size_t)(rowBase + ty * 8 + i) * N + colBase + tx * 8;
        *(float4*)(crow)     = make_float4(acc[i][0], acc[i][1], acc[i][2], acc[i][3]);
        *(float4*)(crow + 4) = make_float4(acc[i][4], acc[i][5], acc[i][6], acc[i][7]);
    }
}

// ---------------------------------------------------------------------------
// RoPE: in-place on t with layout [B, S, nheads, 128]; pairs (2i, 2i+1)
// ---------------------------------------------------------------------------
__global__ void rope_kernel(float* __restrict__ t,
                            const float* __restrict__ fc,
                            const float* __restrict__ fs,
                            int nheads, int total)
{
    int idx = blockIdx.x * blockDim.x + threadIdx.x;
    if (idx >= total) return;
    int i = idx & 63;
    int h = (idx >> 6) % nheads;
    int s = (idx / (64 * nheads)) % S_;
    int b = idx / (64 * nheads * S_);
    float c  = fc[s * 64 + i];
    float sn = fs[s * 64 + i];
    float2* p = (float2*)(t + (((size_t)(b * S_ + s) * nheads + h) * HD_) + 2 * i);
    float2 v = *p;
    *p = make_float2(v.x * c - v.y * sn, v.x * sn + v.y * c);
}

// ---------------------------------------------------------------------------
// Flash attention fp32.  Grid: (S/64, H, B).  Block: 256.
// Q tile 64x128 (smem, transposed), KV tile 64 rows; K and V share one buffer.
// Online softmax; per-row (m,l) replicated across 4 threads/row (tid>>2 = row).
// ---------------------------------------------------------------------------
#define ATTN_SMEM_FLOATS (8192 + 8192 + 4096 + 4096 + 64)
#define ATTN_SMEM_BYTES  (ATTN_SMEM_FLOATS * 4)

__global__ void __launch_bounds__(256) attn_kernel(const float* __restrict__ Qg,
                                                   const float* __restrict__ Kg,
                                                   const float* __restrict__ Vg,
                                                   float* __restrict__ Og)
{
    extern __shared__ float sm[];
    float* Qt    = sm;                 // [128][64]  Qt[d*64 + i]
    float* KV    = Qt + 8192;          // K phase: Kt[d*64+j]; V phase: Vs[j*128+d]
    float* Ssm   = KV + 8192;          // [64][64]
    float* Pt    = Ssm + 4096;         // [64][64]  Pt[j*64 + i]
    float* alpha = Pt + 4096;          // [64]

    const int tid = threadIdx.x;
    const int ty  = tid >> 4;          // 0..15
    const int tx  = tid & 15;          // 0..15
    const int qtile = blockIdx.x;
    const int h     = blockIdx.y;
    const int b     = blockIdx.z;
    const int hk    = h >> 2;
    const float scale = 0.08838834764831845f;   // 1/sqrt(128)

    const size_t qrow0 = (size_t)b * S_ + qtile * 64;

    // Load Q tile transposed
    #pragma unroll
    for (int it = 0; it < 8; it++) {
        int idx = tid + it * 256;           // 0..2047 float4 slots
        int r   = idx >> 5;                 // 0..63
        int d4  = (idx & 31) * 4;           // 0..124
        float4 v = *(const float4*)(Qg + (qrow0 + r) * D_ + h * HD_ + d4);
        Qt[(d4 + 0) * 64 + r] = v.x;
        Qt[(d4 + 1) * 64 + r] = v.y;
        Qt[(d4 + 2) * 64 + r] = v.z;
        Qt[(d4 + 3) * 64 + r] = v.w;
    }

    float o[4][8];
    #pragma unroll
    for (int i = 0; i < 4; i++)
        #pragma unroll
        for (int j = 0; j < 8; j++) o[i][j] = 0.f;

    float m_r = -INFINITY, l_r = 0.f;   // row stats, replicated in 4 thr/row
    const int srow = tid >> 2;          // softmax row
    const int squad = tid & 3;          // quarter of the row

    for (int t = 0; t < S_ / 64; t++) {
        __syncthreads();   // KV buffer free; Qt visible (first iter)

        // K tile (transposed into KV)
        const size_t krow0 = (size_t)b * S_ + t * 64;
        #pragma unroll
        for (int it = 0; it < 8; it++) {
            int idx = tid + it * 256;
            int r   = idx >> 5;
            int d4  = (idx & 31) * 4;
            float4 v = *(const float4*)(Kg + (krow0 + r) * KVD_ + hk * HD_ + d4);
            KV[(d4 + 0) * 64 + r] = v.x;
            KV[(d4 + 1) * 64 + r] = v.y;
            KV[(d4 + 2) * 64 + r] = v.z;
            KV[(d4 + 3) * 64 + r] = v.w;
        }
        __syncthreads();

        // S = Q K^T * scale  (outer product over d)
        {
            float s_[4][4];
            #pragma unroll
            for (int i = 0; i < 4; i++)
                #pragma unroll
                for (int j = 0; j < 4; j++) s_[i][j] = 0.f;
            #pragma unroll 4
            for (int d = 0; d < HD_; d++) {
                float4 q4 = *(const float4*)&Qt[d * 64 + ty * 4];
                float4 k4 = *(const float4*)&KV[d * 64 + tx * 4];
                float qv[4] = {q4.x, q4.y, q4.z, q4.w};
                float kv[4] = {k4.x, k4.y, k4.z, k4.w};
                #pragma unroll
                for (int i = 0; i < 4; i++)
                    #pragma unroll
                    for (int j = 0; j < 4; j++)
                        s_[i][j] += qv[i] * kv[j];
            }
            #pragma unroll
            for (int i = 0; i < 4; i++)
                *(float4*)&Ssm[(ty * 4 + i) * 64 + tx * 4] =
                    make_float4(s_[i][0] * scale, s_[i][1] * scale,
                                s_[i][2] * scale, s_[i][3] * scale);
        }
        __syncthreads();

        // V tile load (overwrites K in KV)
        #pragma unroll
        for (int it = 0; it < 8; it++) {
            int idx = tid + it * 256;
            int r   = idx >> 5;
            int d4  = (idx & 31) * 4;
            float4 v = *(const float4*)(Vg + (krow0 + r) * KVD_ + hk * HD_ + d4);
            *(float4*)&KV[r * 128 + d4] = v;
        }

        // Online softmax: 4 threads per row, each scans 16 cols
        {
            float mx = -INFINITY;
            #pragma unroll
            for (int jj = 0; jj < 16; jj++)
                mx = fmaxf(mx, Ssm[srow * 64 + squad * 16 + jj]);
            mx = fmaxf(mx, __shfl_xor_sync(0xFFFFFFFFu, mx, 1));
            mx = fmaxf(mx, __shfl_xor_sync(0xFFFFFFFFu, mx, 2));
            float mnew = fmaxf(m_r, mx);
            float al   = __expf(m_r - mnew);   // 0 when m_r == -inf
            float sum  = 0.f;
            #pragma unroll
            for (int jj = 0; jj < 16; jj++) {
                int j = squad * 16 + jj;
                float p = __expf(Ssm[srow * 64 + j] - mnew);
                Pt[j * 64 + srow] = p;
                sum += p;
            }
            sum += __shfl_xor_sync(0xFFFFFFFFu, sum, 1);
            sum += __shfl_xor_sync(0xFFFFFFFFu, sum, 2);
            l_r = l_r * al + sum;
            m_r = mnew;
            if (squad == 0) alpha[srow] = al;
        }
        __syncthreads();

        // O = alpha*O + P @ V
        {
            float al0 = alpha[ty * 4 + 0];
            float al1 = alpha[ty * 4 + 1];
            float al2 = alpha[ty * 4 + 2];
            float al3 = alpha[ty * 4 + 3];
            #pragma unroll
            for (int j = 0; j < 8; j++) {
                o[0][j] *= al0; o[1][j] *= al1; o[2][j] *= al2; o[3][j] *= al3;
            }
            #pragma unroll 8
            for (int j = 0; j < 64; j++) {
                float4 p4 = *(const float4*)&Pt[j * 64 + ty * 4];
                float4 v0 = *(const float4*)&KV[j * 128 + tx * 8];
                float4 v1 = *(const float4*)&KV[j * 128 + tx * 8 + 4];
                float vv[8] = {v0.x, v0.y, v0.z, v0.w, v1.x, v1.y, v1.z, v1.w};
                float pv[4] = {p4.x, p4.y, p4.z, p4.w};
                #pragma unroll
                for (int i = 0; i < 4; i++)
                    #pragma unroll
                    for (int jj = 0; jj < 8; jj++)
                        o[i][jj] += pv[i] * vv[jj];
            }
        }
    }

    __syncthreads();
    if (squad == 0) alpha[srow] = 1.f / l_r;   // reuse alpha for 1/l
    __syncthreads();

    #pragma unroll
    for (int i = 0; i < 4; i++) {
        int r = ty * 4 + i;
        float inv = alpha[r];
        float* dst = Og + (qrow0 + r) * D_ + h * HD_ + tx * 8;
        *(float4*)(dst)     = make_float4(o[i][0] * inv, o[i][1] * inv,
                                          o[i][2] * inv, o[i][3] * inv);
        *(float4*)(dst + 4) = make_float4(o[i][4] * inv, o[i][5] * inv,
                                          o[i][6] * inv, o[i][7] * inv);
    }
}

// ---------------------------------------------------------------------------
// Launch
// ---------------------------------------------------------------------------
extern "C" void kernel_launch(void* const* d_in, const int* in_sizes, int n_in,
                              void* d_out, int out_size)
{
    const float* x  = (const float*)d_in[0];
    const float* fc = (const float*)d_in[1];
    const float* fs = (const float*)d_in[2];
    const float* wq = (const float*)d_in[3];
    const float* wk = (const float*)d_in[4];
    const float* wv = (const float*)d_in[5];
    const float* wo = (const float*)d_in[6];
    // d_in[7] = start (always 0 for this problem)
    float* out = (float*)d_out;

    float *xq, *xk, *xv, *attn;
    cudaGetSymbolAddress((void**)&xq,   g_xq);
    cudaGetSymbolAddress((void**)&xk,   g_xk);
    cudaGetSymbolAddress((void**)&xv,   g_xv);
    cudaGetSymbolAddress((void**)&attn, g_attn);

    cudaFuncSetAttribute(attn_kernel,
                         cudaFuncAttributeMaxDynamicSharedMemorySize,
                         ATTN_SMEM_BYTES);

    const int M = B_ * S_;   // 4096

    dim3 gBig(D_ / 128, M / 128);     // 32 x 32
    dim3 gKV(KVD_ / 128, M / 128);    // 8 x 32

    // QKV projections
    sgemm128<<<gBig, 256>>>(x, wq, xq, M, D_,  D_);
    sgemm128<<<gKV,  256>>>(x, wk, xk, M, KVD_, D_);
    sgemm128<<<gKV,  256>>>(x, wv, xv, M, KVD_, D_);

    // RoPE
    {
        int totq = B_ * S_ * H_  * (HD_ / 2);
        int totk = B_ * S_ * HKV_ * (HD_ / 2);
        rope_kernel<<<(totq + 255) / 256, 256>>>(xq, fc, fs, H_,  totq);
        rope_kernel<<<(totk + 255) / 256, 256>>>(xk, fc, fs, HKV_, totk);
    }

    // Attention
    {
        dim3 ga(S_ / 64, H_, B_);
        attn_kernel<<<ga, 256, ATTN_SMEM_BYTES>>>(xq, xk, xv, attn);
    }

    // Output projection
    sgemm128<<<gBig, 256>>>(attn, wo, out, M, D_, D_);
}

// round 3
// speedup vs baseline: 1.7266x; 1.7266x over previous
#include <cuda_runtime.h>
#include <cuda_bf16.h>
#include <math.h>
#include <cstdint>

#define B_    4
#define S_    1024
#define D_    4096
#define H_    32
#define HKV_  8
#define HD_   128
#define KVD_  (HKV_*HD_)   // 1024
#define M_    (B_*S_)      // 4096

// ---------------- scratch (static device globals) ----------------
__device__ float g_xq[B_*S_*D_];        // 64 MB
__device__ float g_xk[B_*S_*KVD_];      // 16 MB
__device__ float g_xv[B_*S_*KVD_];      // 16 MB
__device__ float g_attn[B_*S_*D_];      // 64 MB
__device__ __nv_bfloat16 g_ah[M_*D_];   // 32 MB (x / attn hi)
__device__ __nv_bfloat16 g_al[M_*D_];   // 32 MB (x / attn lo)
__device__ __nv_bfloat16 g_wqh[D_*D_],   g_wql[D_*D_];
__device__ __nv_bfloat16 g_wkh[D_*KVD_], g_wkl[D_*KVD_];
__device__ __nv_bfloat16 g_wvh[D_*KVD_], g_wvl[D_*KVD_];
__device__ __nv_bfloat16 g_woh[D_*D_],   g_wol[D_*D_];

// ---------------- PTX helpers (baseline compute_103 features only) ----------
__device__ __forceinline__ uint32_t smem_u32(const void* p) {
    uint32_t a;
    asm("{ .reg .u64 t; cvta.to.shared.u64 t, %1; cvt.u32.u64 %0, t; }" : "=r"(a) : "l"(p));
    return a;
}

#define SW128(off) ((off) ^ (((off) >> 3) & 0x70))

#define CP16(dst, src) asm volatile("cp.async.cg.shared.global [%0], [%1], 16;" :: "r"(dst), "l"(src))
#define CP_COMMIT()    asm volatile("cp.async.commit_group;" ::: "memory")

#define LDSM4(r0, r1, r2, r3, a)                                             \
    asm volatile("ldmatrix.sync.aligned.m8n8.x4.shared.b16 {%0,%1,%2,%3}, [%4];" \
        : "=r"(r0), "=r"(r1), "=r"(r2), "=r"(r3) : "r"(a))

#define MMA_BF16(ac, ar, br)                                                 \
    asm volatile("mma.sync.aligned.m16n8k16.row.col.f32.bf16.bf16.f32 "      \
        "{%0,%1,%2,%3}, {%4,%5,%6,%7}, {%8,%9}, {%0,%1,%2,%3};"              \
        : "+f"((ac)[0]), "+f"((ac)[1]), "+f"((ac)[2]), "+f"((ac)[3])         \
        : "r"((ar)[0]), "r"((ar)[1]), "r"((ar)[2]), "r"((ar)[3]),            \
          "r"((br)[0]), "r"((br)[1]))

// ---------------------------------------------------------------------------
// Warp-MMA GEMM: C[M,N] fp32 = (Ah+Al)[M,K] @ (Bh+Bl)^T,  B stored [N,K].
// Drops Al*Bl (~2^-18 relative). Grid: (N/128, M/128). Block: 256 (8 warps,
// 2x4; warp tile 64x32). BK=64 (128B rows, SW128), 3-stage cp.async pipeline.
// ---------------------------------------------------------------------------
#define STAGE_BYTES 65536
#define GEMM_SMEM  (3*STAGE_BYTES + 128)

__global__ void __launch_bounds__(256, 1) gemm_tc(const __nv_bfloat16* __restrict__ Ah,
                                                  const __nv_bfloat16* __restrict__ Al,
                                                  const __nv_bfloat16* __restrict__ Bh,
                                                  const __nv_bfloat16* __restrict__ Bl,
                                                  float* __restrict__ C, int N, int K)
{
    extern __shared__ char smem[];
    const uint32_t sb   = smem_u32(smem);
    const uint32_t base = (sb + 127u) & ~127u;
    const int tid  = threadIdx.x;
    const int lane = tid & 31;
    const int wid  = tid >> 5;
    const int wm   = wid & 1;       // 0..1 : 64-row group
    const int wn   = wid >> 1;      // 0..3 : 32-col group
    const int rowBase = blockIdx.y * 128;
    const int colBase = blockIdx.x * 128;

    float acc[4][4][4];
    #pragma unroll
    for (int mi = 0; mi < 4; mi++)
        #pragma unroll
        for (int ni = 0; ni < 4; ni++)
            #pragma unroll
            for (int r = 0; r < 4; r++) acc[mi][ni][r] = 0.f;

    const int nc = K >> 6;   // 64-wide K chunks

    #define LOAD_CHUNK(c) do {                                                     \
        const int _s = (c) % 3;                                                    \
        const uint32_t _st = base + _s*STAGE_BYTES;                                \
        const int _kb = (c) * 64;                                                  \
        _Pragma("unroll")                                                          \
        for (int _i = 0; _i < 4; _i++) {                                           \
            const int _id  = tid + _i*256;                                         \
            const int _row = _id >> 3;                                             \
            const int _u   = _id & 7;                                              \
            const uint32_t _sw = SW128((uint32_t)(_row*128 + _u*16));              \
            const size_t _ao = (size_t)(rowBase + _row)*K + _kb + _u*8;            \
            const size_t _bo = (size_t)(colBase + _row)*K + _kb + _u*8;            \
            CP16(_st +         _sw, Ah + _ao);                                     \
            CP16(_st + 16384 + _sw, Al + _ao);                                     \
            CP16(_st + 32768 + _sw, Bh + _bo);                                     \
            CP16(_st + 49152 + _sw, Bl + _bo);                                     \
        }                                                                          \
        CP_COMMIT();                                                               \
    } while (0)

    LOAD_CHUNK(0); LOAD_CHUNK(1);

    for (int c = 0; c < nc; c++) {
        if (c == nc - 1) asm volatile("cp.async.wait_group 0;" ::: "memory");
        else             asm volatile("cp.async.wait_group 1;" ::: "memory");
        __syncthreads();
        if (c + 2 < nc) LOAD_CHUNK(c + 2);

        const uint32_t stA  = base + (c % 3)*STAGE_BYTES;
        const uint32_t stAl = stA + 16384;
        const uint32_t stB  = stA + 32768;
        const uint32_t stBl = stA + 49152;

        #pragma unroll
        for (int ks = 0; ks < 4; ks++) {
            const uint32_t kb = (uint32_t)(ks*32 + (lane >> 4)*16);

            uint32_t ah[4][4], al4[4][4];
            #pragma unroll
            for (int mi = 0; mi < 4; mi++) {
                const uint32_t off = (uint32_t)((wm*64 + mi*16 + (lane & 15)) * 128) + kb;
                const uint32_t sw  = SW128(off);
                LDSM4(ah[mi][0],  ah[mi][1],  ah[mi][2],  ah[mi][3],  stA  + sw);
                LDSM4(al4[mi][0], al4[mi][1], al4[mi][2], al4[mi][3], stAl + sw);
            }
            uint32_t bh[4][2], bl4[4][2];
            #pragma unroll
            for (int nj = 0; nj < 2; nj++) {
                const uint32_t off = (uint32_t)((wn*32 + nj*16 + (lane & 15)) * 128) + kb;
                const uint32_t sw  = SW128(off);
                LDSM4(bh[2*nj][0],  bh[2*nj+1][0],  bh[2*nj][1],  bh[2*nj+1][1],  stB  + sw);
                LDSM4(bl4[2*nj][0], bl4[2*nj+1][0], bl4[2*nj][1], bl4[2*nj+1][1], stBl + sw);
            }

            #pragma unroll
            for (int mi = 0; mi < 4; mi++)
                #pragma unroll
                for (int ni = 0; ni < 4; ni++) {
                    MMA_BF16(acc[mi][ni], ah[mi],  bh[ni]);
                    MMA_BF16(acc[mi][ni], ah[mi],  bl4[ni]);
                    MMA_BF16(acc[mi][ni], al4[mi], bh[ni]);
                }
        }
    }

    // Epilogue: C fragments -> global fp32
    #pragma unroll
    for (int mi = 0; mi < 4; mi++) {
        const int r0 = rowBase + wm*64 + mi*16 + (lane >> 2);
        #pragma unroll
        for (int ni = 0; ni < 4; ni++) {
            const int c0 = colBase + wn*32 + ni*8 + (lane & 3)*2;
            *(float2*)(C + (size_t)r0*N + c0)       = make_float2(acc[mi][ni][0], acc[mi][ni][1]);
            *(float2*)(C + (size_t)(r0 + 8)*N + c0) = make_float2(acc[mi][ni][2], acc[mi][ni][3]);
        }
    }
    #undef LOAD_CHUNK
}

// ---------------------------------------------------------------------------
// fp32 -> (hi, lo) bf16 split, same layout
// ---------------------------------------------------------------------------
__global__ void split_fp32(const float* __restrict__ in,
                           __nv_bfloat16* __restrict__ hi,
                           __nv_bfloat16* __restrict__ lo, int n)
{
    int i = (blockIdx.x * blockDim.x + threadIdx.x) << 2;
    if (i >= n) return;
    float4 v = *(const float4*)(in + i);
    float vv[4] = {v.x, v.y, v.z, v.w};
    __nv_bfloat16 h[4], l[4];
    #pragma unroll
    for (int j = 0; j < 4; j++) {
        h[j] = __float2bfloat16(vv[j]);
        l[j] = __float2bfloat16(vv[j] - __bfloat162float(h[j]));
    }
    ((__nv_bfloat162*)(hi + i))[0] = __nv_bfloat162(h[0], h[1]);
    ((__nv_bfloat162*)(hi + i))[1] = __nv_bfloat162(h[2], h[3]);
    ((__nv_bfloat162*)(lo + i))[0] = __nv_bfloat162(l[0], l[1]);
    ((__nv_bfloat162*)(lo + i))[1] = __nv_bfloat162(l[2], l[3]);
}

// ---------------------------------------------------------------------------
// w[K,N] fp32 -> wt_hi/wt_lo [N,K] bf16 (transpose + split)
// ---------------------------------------------------------------------------
__global__ void __launch_bounds__(256) transpose_split(const float* __restrict__ w,
                                                       __nv_bfloat16* __restrict__ thi,
                                                       __nv_bfloat16* __restrict__ tlo,
                                                       int K, int N)
{
    __shared__ float t[32][33];
    const int tid = threadIdx.x;
    const int tx = tid & 31, ty = tid >> 5;
    const int n0 = blockIdx.x * 32, k0 = blockIdx.y * 32;
    #pragma unroll
    for (int r = 0; r < 4; r++)
        t[ty + r*8][tx] = w[(size_t)(k0 + ty + r*8) * N + n0 + tx];
    __syncthreads();
    #pragma unroll
    for (int r = 0; r < 4; r++) {
        float v = t[tx][ty + r*8];
        __nv_bfloat16 h = __float2bfloat16(v);
        __nv_bfloat16 l = __float2bfloat16(v - __bfloat162float(h));
        size_t o = (size_t)(n0 + ty + r*8) * K + k0 + tx;
        thi[o] = h;
        tlo[o] = l;
    }
}

// ---------------------------------------------------------------------------
// RoPE
// ---------------------------------------------------------------------------
__global__ void rope_kernel(float* __restrict__ t,
                            const float* __restrict__ fc,
                            const float* __restrict__ fs,
                            int nheads, int total)
{
    int idx = blockIdx.x * blockDim.x + threadIdx.x;
    if (idx >= total) return;
    int i = idx & 63;
    int h = (idx >> 6) % nheads;
    int s = (idx / (64 * nheads)) % S_;
    int b = idx / (64 * nheads * S_);
    float c  = fc[s * 64 + i];
    float sn = fs[s * 64 + i];
    float2* p = (float2*)(t + (((size_t)(b * S_ + s) * nheads + h) * HD_) + 2 * i);
    float2 v = *p;
    *p = make_float2(v.x * c - v.y * sn, v.x * sn + v.y * c);
}

// ---------------------------------------------------------------------------
// Flash attention fp32 (unchanged)
// ---------------------------------------------------------------------------
#define ATTN_SMEM_FLOATS (8192 + 8192 + 4096 + 4096 + 64)
#define ATTN_SMEM_BYTES  (ATTN_SMEM_FLOATS * 4)

__global__ void __launch_bounds__(256) attn_kernel(const float* __restrict__ Qg,
                                                   const float* __restrict__ Kg,
                                                   const float* __restrict__ Vg,
                                                   float* __restrict__ Og)
{
    extern __shared__ float sm[];
    float* Qt    = sm;
    float* KV    = Qt + 8192;
    float* Ssm   = KV + 8192;
    float* Pt    = Ssm + 4096;
    float* alpha = Pt + 4096;

    const int tid = threadIdx.x;
    const int ty  = tid >> 4;
    const int tx  = tid & 15;
    const int qtile = blockIdx.x;
    const int h     = blockIdx.y;
    const int b     = blockIdx.z;
    const int hk    = h >> 2;
    const float scale = 0.08838834764831845f;

    const size_t qrow0 = (size_t)b * S_ + qtile * 64;

    #pragma unroll
    for (int it = 0; it < 8; it++) {
        int idx = tid + it * 256;
        int r   = idx >> 5;
        int d4  = (idx & 31) * 4;
        float4 v = *(const float4*)(Qg + (qrow0 + r) * D_ + h * HD_ + d4);
        Qt[(d4 + 0) * 64 + r] = v.x;
        Qt[(d4 + 1) * 64 + r] = v.y;
        Qt[(d4 + 2) * 64 + r] = v.z;
        Qt[(d4 + 3) * 64 + r] = v.w;
    }

    float o[4][8];
    #pragma unroll
    for (int i = 0; i < 4; i++)
        #pragma unroll
        for (int j = 0; j < 8; j++) o[i][j] = 0.f;

    float m_r = -INFINITY, l_r = 0.f;
    const int srow = tid >> 2;
    const int squad = tid & 3;

    for (int t = 0; t < S_ / 64; t++) {
        __syncthreads();

        const size_t krow0 = (size_t)b * S_ + t * 64;
        #pragma unroll
        for (int it = 0; it < 8; it++) {
            int idx = tid + it * 256;
            int r   = idx >> 5;
            int d4  = (idx & 31) * 4;
            float4 v = *(const float4*)(Kg + (krow0 + r) * KVD_ + hk * HD_ + d4);
            KV[(d4 + 0) * 64 + r] = v.x;
            KV[(d4 + 1) * 64 + r] = v.y;
            KV[(d4 + 2) * 64 + r] = v.z;
            KV[(d4 + 3) * 64 + r] = v.w;
        }
        __syncthreads();

        {
            float s_[4][4];
            #pragma unroll
            for (int i = 0; i < 4; i++)
                #pragma unroll
                for (int j = 0; j < 4; j++) s_[i][j] = 0.f;
            #pragma unroll 4
            for (int d = 0; d < HD_; d++) {
                float4 q4 = *(const float4*)&Qt[d * 64 + ty * 4];
                float4 k4 = *(const float4*)&KV[d * 64 + tx * 4];
                float qv[4] = {q4.x, q4.y, q4.z, q4.w};
                float kv[4] = {k4.x, k4.y, k4.z, k4.w};
                #pragma unroll
                for (int i = 0; i < 4; i++)
                    #pragma unroll
                    for (int j = 0; j < 4; j++)
                        s_[i][j] += qv[i] * kv[j];
            }
            #pragma unroll
            for (int i = 0; i < 4; i++)
                *(float4*)&Ssm[(ty * 4 + i) * 64 + tx * 4] =
                    make_float4(s_[i][0] * scale, s_[i][1] * scale,
                                s_[i][2] * scale, s_[i][3] * scale);
        }
        __syncthreads();

        #pragma unroll
        for (int it = 0; it < 8; it++) {
            int idx = tid + it * 256;
            int r   = idx >> 5;
            int d4  = (idx & 31) * 4;
            float4 v = *(const float4*)(Vg + (krow0 + r) * KVD_ + hk * HD_ + d4);
            *(float4*)&KV[r * 128 + d4] = v;
        }

        {
            float mx = -INFINITY;
            #pragma unroll
            for (int jj = 0; jj < 16; jj++)
                mx = fmaxf(mx, Ssm[srow * 64 + squad * 16 + jj]);
            mx = fmaxf(mx, __shfl_xor_sync(0xFFFFFFFFu, mx, 1));
            mx = fmaxf(mx, __shfl_xor_sync(0xFFFFFFFFu, mx, 2));
            float mnew = fmaxf(m_r, mx);
            float al   = __expf(m_r - mnew);
            float sum  = 0.f;
            #pragma unroll
            for (int jj = 0; jj < 16; jj++) {
                int j = squad * 16 + jj;
                float p = __expf(Ssm[srow * 64 + j] - mnew);
                Pt[j * 64 + srow] = p;
                sum += p;
            }
            sum += __shfl_xor_sync(0xFFFFFFFFu, sum, 1);
            sum += __shfl_xor_sync(0xFFFFFFFFu, sum, 2);
            l_r = l_r * al + sum;
            m_r = mnew;
            if (squad == 0) alpha[srow] = al;
        }
        __syncthreads();

        {
            float al0 = alpha[ty * 4 + 0];
            float al1 = alpha[ty * 4 + 1];
            float al2 = alpha[ty * 4 + 2];
            float al3 = alpha[ty * 4 + 3];
            #pragma unroll
            for (int j = 0; j < 8; j++) {
                o[0][j] *= al0; o[1][j] *= al1; o[2][j] *= al2; o[3][j] *= al3;
            }
            #pragma unroll 8
            for (int j = 0; j < 64; j++) {
                float4 p4 = *(const float4*)&Pt[j * 64 + ty * 4];
                float4 v0 = *(const float4*)&KV[j * 128 + tx * 8];
                float4 v1 = *(const float4*)&KV[j * 128 + tx * 8 + 4];
                float vv[8] = {v0.x, v0.y, v0.z, v0.w, v1.x, v1.y, v1.z, v1.w};
                float pv[4] = {p4.x, p4.y, p4.z, p4.w};
                #pragma unroll
                for (int i = 0; i < 4; i++)
                    #pragma unroll
                    for (int jj = 0; jj < 8; jj++)
                        o[i][jj] += pv[i] * vv[jj];
            }
        }
    }

    __syncthreads();
    if (squad == 0) alpha[srow] = 1.f / l_r;
    __syncthreads();

    #pragma unroll
    for (int i = 0; i < 4; i++) {
        int r = ty * 4 + i;
        float inv = alpha[r];
        float* dst = Og + (qrow0 + r) * D_ + h * HD_ + tx * 8;
        *(float4*)(dst)     = make_float4(o[i][0] * inv, o[i][1] * inv,
                                          o[i][2] * inv, o[i][3] * inv);
        *(float4*)(dst + 4) = make_float4(o[i][4] * inv, o[i][5] * inv,
                                          o[i][6] * inv, o[i][7] * inv);
    }
}

// ---------------------------------------------------------------------------
// Launch
// ---------------------------------------------------------------------------
extern "C" void kernel_launch(void* const* d_in, const int* in_sizes, int n_in,
                              void* d_out, int out_size)
{
    const float* x  = (const float*)d_in[0];
    const float* fc = (const float*)d_in[1];
    const float* fs = (const float*)d_in[2];
    const float* wq = (const float*)d_in[3];
    const float* wk = (const float*)d_in[4];
    const float* wv = (const float*)d_in[5];
    const float* wo = (const float*)d_in[6];
    float* out = (float*)d_out;

    float *xq, *xk, *xv, *attn;
    cudaGetSymbolAddress((void**)&xq,   g_xq);
    cudaGetSymbolAddress((void**)&xk,   g_xk);
    cudaGetSymbolAddress((void**)&xv,   g_xv);
    cudaGetSymbolAddress((void**)&attn, g_attn);
    __nv_bfloat16 *ah, *al, *wqh, *wql, *wkh, *wkl, *wvh, *wvl, *woh, *wol;
    cudaGetSymbolAddress((void**)&ah,  g_ah);
    cudaGetSymbolAddress((void**)&al,  g_al);
    cudaGetSymbolAddress((void**)&wqh, g_wqh);
    cudaGetSymbolAddress((void**)&wql, g_wql);
    cudaGetSymbolAddress((void**)&wkh, g_wkh);
    cudaGetSymbolAddress((void**)&wkl, g_wkl);
    cudaGetSymbolAddress((void**)&wvh, g_wvh);
    cudaGetSymbolAddress((void**)&wvl, g_wvl);
    cudaGetSymbolAddress((void**)&woh, g_woh);
    cudaGetSymbolAddress((void**)&wol, g_wol);

    cudaFuncSetAttribute(gemm_tc, cudaFuncAttributeMaxDynamicSharedMemorySize, GEMM_SMEM);
    cudaFuncSetAttribute(attn_kernel, cudaFuncAttributeMaxDynamicSharedMemorySize, ATTN_SMEM_BYTES);

    // 1) operand conversions
    split_fp32<<<(M_*D_/4 + 255)/256, 256>>>(x, ah, al, M_*D_);
    transpose_split<<<dim3(D_/32,  D_/32), 256>>>(wq, wqh, wql, D_, D_);
    transpose_split<<<dim3(KVD_/32, D_/32), 256>>>(wk, wkh, wkl, D_, KVD_);
    transpose_split<<<dim3(KVD_/32, D_/32), 256>>>(wv, wvh, wvl, D_, KVD_);
    transpose_split<<<dim3(D_/32,  D_/32), 256>>>(wo, woh, wol, D_, D_);

    // 2) QKV projections (tensor cores via mma.sync)
    gemm_tc<<<dim3(D_/128,   M_/128), 256, GEMM_SMEM>>>(ah, al, wqh, wql, xq, D_,   D_);
    gemm_tc<<<dim3(KVD_/128, M_/128), 256, GEMM_SMEM>>>(ah, al, wkh, wkl, xk, KVD_, D_);
    gemm_tc<<<dim3(KVD_/128, M_/128), 256, GEMM_SMEM>>>(ah, al, wvh, wvl, xv, KVD_, D_);

    // 3) RoPE
    {
        int totq = B_ * S_ * H_   * (HD_ / 2);
        int totk = B_ * S_ * HKV_ * (HD_ / 2);
        rope_kernel<<<(totq + 255)/256, 256>>>(xq, fc, fs, H_,   totq);
        rope_kernel<<<(totk + 255)/256, 256>>>(xk, fc, fs, HKV_, totk);
    }

    // 4) attention (fp32 flash)
    {
        dim3 ga(S_/64, H_, B_);
        attn_kernel<<<ga, 256, ATTN_SMEM_BYTES>>>(xq, xk, xv, attn);
    }

    // 5) output projection
    split_fp32<<<(M_*D_/4 + 255)/256, 256>>>(attn, ah, al, M_*D_);
    gemm_tc<<<dim3(D_/128, M_/128), 256, GEMM_SMEM>>>(ah, al, woh, wol, out, D_, D_);
}

// round 4
// speedup vs baseline: 2.8721x; 1.6635x over previous
#include <cuda_runtime.h>
#include <cuda_bf16.h>
#include <math.h>
#include <cstdint>

#define B_    4
#define S_    1024
#define D_    4096
#define H_    32
#define HKV_  8
#define HD_   128
#define KVD_  (HKV_*HD_)   // 1024
#define M_    (B_*S_)      // 4096

// ---------------- scratch (static device globals) ----------------
__device__ float g_xq[M_*D_];
__device__ float g_xk[M_*KVD_];
__device__ float g_xv[M_*KVD_];
__device__ float g_attn[M_*D_];
__device__ __nv_bfloat16 g_ah[M_*D_];   // x split hi / later Q-rope hi / later attn hi
__device__ __nv_bfloat16 g_al[M_*D_];
__device__ __nv_bfloat16 g_kh[M_*KVD_], g_kl[M_*KVD_];
__device__ __nv_bfloat16 g_vth[M_*KVD_], g_vtl[M_*KVD_];   // V transposed [b][hkv][d][s]
__device__ __nv_bfloat16 g_wqh[D_*D_],   g_wql[D_*D_];
__device__ __nv_bfloat16 g_wkh[D_*KVD_], g_wkl[D_*KVD_];
__device__ __nv_bfloat16 g_wvh[D_*KVD_], g_wvl[D_*KVD_];
__device__ __nv_bfloat16 g_woh[D_*D_],   g_wol[D_*D_];

// ---------------- PTX helpers ----------------
__device__ __forceinline__ uint32_t smem_u32(const void* p) {
    uint32_t a;
    asm("{ .reg .u64 t; cvta.to.shared.u64 t, %1; cvt.u32.u64 %0, t; }" : "=r"(a) : "l"(p));
    return a;
}
#define SW128(off) ((off) ^ (((off) >> 3) & 0x70))
#define CP16(dst, src) asm volatile("cp.async.cg.shared.global [%0], [%1], 16;" :: "r"(dst), "l"(src))
#define CP_COMMIT()    asm volatile("cp.async.commit_group;" ::: "memory")
#define LDSM4(r0, r1, r2, r3, a)                                             \
    asm volatile("ldmatrix.sync.aligned.m8n8.x4.shared.b16 {%0,%1,%2,%3}, [%4];" \
        : "=r"(r0), "=r"(r1), "=r"(r2), "=r"(r3) : "r"(a))
#define MMA_BF16(ac, ar, br)                                                 \
    asm volatile("mma.sync.aligned.m16n8k16.row.col.f32.bf16.bf16.f32 "      \
        "{%0,%1,%2,%3}, {%4,%5,%6,%7}, {%8,%9}, {%0,%1,%2,%3};"              \
        : "+f"((ac)[0]), "+f"((ac)[1]), "+f"((ac)[2]), "+f"((ac)[3])         \
        : "r"((ar)[0]), "r"((ar)[1]), "r"((ar)[2]), "r"((ar)[3]),            \
          "r"((br)[0]), "r"((br)[1]))

// ---------------------------------------------------------------------------
// Warp-MMA GEMM (unchanged from R3): C = (Ah+Al) @ (Bh+Bl)^T, B stored [N,K]
// ---------------------------------------------------------------------------
#define STAGE_BYTES 65536
#define GEMM_SMEM  (3*STAGE_BYTES + 128)

__global__ void __launch_bounds__(256, 1) gemm_tc(const __nv_bfloat16* __restrict__ Ah,
                                                  const __nv_bfloat16* __restrict__ Al,
                                                  const __nv_bfloat16* __restrict__ Bh,
                                                  const __nv_bfloat16* __restrict__ Bl,
                                                  float* __restrict__ C, int N, int K)
{
    extern __shared__ char smem[];
    const uint32_t sb   = smem_u32(smem);
    const uint32_t base = (sb + 127u) & ~127u;
    const int tid  = threadIdx.x;
    const int lane = tid & 31;
    const int wid  = tid >> 5;
    const int wm   = wid & 1;
    const int wn   = wid >> 1;
    const int rowBase = blockIdx.y * 128;
    const int colBase = blockIdx.x * 128;

    float acc[4][4][4];
    #pragma unroll
    for (int mi = 0; mi < 4; mi++)
        #pragma unroll
        for (int ni = 0; ni < 4; ni++)
            #pragma unroll
            for (int r = 0; r < 4; r++) acc[mi][ni][r] = 0.f;

    const int nc = K >> 6;

    #define LOAD_CHUNK(c) do {                                                     \
        const int _s = (c) % 3;                                                    \
        const uint32_t _st = base + _s*STAGE_BYTES;                                \
        const int _kb = (c) * 64;                                                  \
        _Pragma("unroll")                                                          \
        for (int _i = 0; _i < 4; _i++) {                                           \
            const int _id  = tid + _i*256;                                         \
            const int _row = _id >> 3;                                             \
            const int _u   = _id & 7;                                              \
            const uint32_t _sw = SW128((uint32_t)(_row*128 + _u*16));              \
            const size_t _ao = (size_t)(rowBase + _row)*K + _kb + _u*8;            \
            const size_t _bo = (size_t)(colBase + _row)*K + _kb + _u*8;            \
            CP16(_st +         _sw, Ah + _ao);                                     \
            CP16(_st + 16384 + _sw, Al + _ao);                                     \
            CP16(_st + 32768 + _sw, Bh + _bo);                                     \
            CP16(_st + 49152 + _sw, Bl + _bo);                                     \
        }                                                                          \
        CP_COMMIT();                                                               \
    } while (0)

    LOAD_CHUNK(0); LOAD_CHUNK(1);

    for (int c = 0; c < nc; c++) {
        if (c == nc - 1) asm volatile("cp.async.wait_group 0;" ::: "memory");
        else             asm volatile("cp.async.wait_group 1;" ::: "memory");
        __syncthreads();
        if (c + 2 < nc) LOAD_CHUNK(c + 2);

        const uint32_t stA  = base + (c % 3)*STAGE_BYTES;
        const uint32_t stAl = stA + 16384;
        const uint32_t stB  = stA + 32768;
        const uint32_t stBl = stA + 49152;

        #pragma unroll
        for (int ks = 0; ks < 4; ks++) {
            const uint32_t kb = (uint32_t)(ks*32 + (lane >> 4)*16);

            uint32_t ah[4][4], al4[4][4];
            #pragma unroll
            for (int mi = 0; mi < 4; mi++) {
                const uint32_t off = (uint32_t)((wm*64 + mi*16 + (lane & 15)) * 128) + kb;
                const uint32_t sw  = SW128(off);
                LDSM4(ah[mi][0],  ah[mi][1],  ah[mi][2],  ah[mi][3],  stA  + sw);
                LDSM4(al4[mi][0], al4[mi][1], al4[mi][2], al4[mi][3], stAl + sw);
            }
            uint32_t bh[4][2], bl4[4][2];
            #pragma unroll
            for (int nj = 0; nj < 2; nj++) {
                const uint32_t off = (uint32_t)((wn*32 + nj*16 + (lane & 15)) * 128) + kb;
                const uint32_t sw  = SW128(off);
                LDSM4(bh[2*nj][0],  bh[2*nj+1][0],  bh[2*nj][1],  bh[2*nj+1][1],  stB  + sw);
                LDSM4(bl4[2*nj][0], bl4[2*nj+1][0], bl4[2*nj][1], bl4[2*nj+1][1], stBl + sw);
            }

            #pragma unroll
            for (int mi = 0; mi < 4; mi++)
                #pragma unroll
                for (int ni = 0; ni < 4; ni++) {
                    MMA_BF16(acc[mi][ni], ah[mi],  bh[ni]);
                    MMA_BF16(acc[mi][ni], ah[mi],  bl4[ni]);
                    MMA_BF16(acc[mi][ni], al4[mi], bh[ni]);
                }
        }
    }

    #pragma unroll
    for (int mi = 0; mi < 4; mi++) {
        const int r0 = rowBase + wm*64 + mi*16 + (lane >> 2);
        #pragma unroll
        for (int ni = 0; ni < 4; ni++) {
            const int c0 = colBase + wn*32 + ni*8 + (lane & 3)*2;
            *(float2*)(C + (size_t)r0*N + c0)       = make_float2(acc[mi][ni][0], acc[mi][ni][1]);
            *(float2*)(C + (size_t)(r0 + 8)*N + c0) = make_float2(acc[mi][ni][2], acc[mi][ni][3]);
        }
    }
    #undef LOAD_CHUNK
}

// ---------------------------------------------------------------------------
// fp32 -> (hi, lo) bf16 split
// ---------------------------------------------------------------------------
__global__ void split_fp32(const float* __restrict__ in,
                           __nv_bfloat16* __restrict__ hi,
                           __nv_bfloat16* __restrict__ lo, int n)
{
    int i = (blockIdx.x * blockDim.x + threadIdx.x) << 2;
    if (i >= n) return;
    float4 v = *(const float4*)(in + i);
    float vv[4] = {v.x, v.y, v.z, v.w};
    __nv_bfloat16 h[4], l[4];
    #pragma unroll
    for (int j = 0; j < 4; j++) {
        h[j] = __float2bfloat16(vv[j]);
        l[j] = __float2bfloat16(vv[j] - __bfloat162float(h[j]));
    }
    ((__nv_bfloat162*)(hi + i))[0] = __nv_bfloat162(h[0], h[1]);
    ((__nv_bfloat162*)(hi + i))[1] = __nv_bfloat162(h[2], h[3]);
    ((__nv_bfloat162*)(lo + i))[0] = __nv_bfloat162(l[0], l[1]);
    ((__nv_bfloat162*)(lo + i))[1] = __nv_bfloat162(l[2], l[3]);
}

// ---------------------------------------------------------------------------
// w[K,N] fp32 -> [N,K] bf16 hi/lo (transpose + split)
// ---------------------------------------------------------------------------
__global__ void __launch_bounds__(256) transpose_split(const float* __restrict__ w,
                                                       __nv_bfloat16* __restrict__ thi,
                                                       __nv_bfloat16* __restrict__ tlo,
                                                       int K, int N)
{
    __shared__ float t[32][33];
    const int tid = threadIdx.x;
    const int tx = tid & 31, ty = tid >> 5;
    const int n0 = blockIdx.x * 32, k0 = blockIdx.y * 32;
    #pragma unroll
    for (int r = 0; r < 4; r++)
        t[ty + r*8][tx] = w[(size_t)(k0 + ty + r*8) * N + n0 + tx];
    __syncthreads();
    #pragma unroll
    for (int r = 0; r < 4; r++) {
        float v = t[tx][ty + r*8];
        __nv_bfloat16 h = __float2bfloat16(v);
        __nv_bfloat16 l = __float2bfloat16(v - __bfloat162float(h));
        size_t o = (size_t)(n0 + ty + r*8) * K + k0 + tx;
        thi[o] = h;
        tlo[o] = l;
    }
}

// ---------------------------------------------------------------------------
// RoPE + bf16 hi/lo split: fp32 in [b,s,nh,128] -> oh/ol bf16 same layout
// ---------------------------------------------------------------------------
__global__ void rope_split(const float* __restrict__ t,
                           const float* __restrict__ fc,
                           const float* __restrict__ fs,
                           __nv_bfloat16* __restrict__ oh,
                           __nv_bfloat16* __restrict__ ol,
                           int nheads, int total)
{
    int idx = blockIdx.x * blockDim.x + threadIdx.x;
    if (idx >= total) return;
    int i = idx & 63;
    int h = (idx >> 6) % nheads;
    int s = (idx / (64 * nheads)) % S_;
    int b = idx / (64 * nheads * S_);
    float c  = fc[s * 64 + i];
    float sn = fs[s * 64 + i];
    size_t off = (((size_t)(b * S_ + s) * nheads + h) * HD_) + 2 * i;
    float2 v = *(const float2*)(t + off);
    float orr = v.x * c - v.y * sn;
    float oii = v.x * sn + v.y * c;
    __nv_bfloat16 h0 = __float2bfloat16(orr);
    __nv_bfloat16 h1 = __float2bfloat16(oii);
    __nv_bfloat16 l0 = __float2bfloat16(orr - __bfloat162float(h0));
    __nv_bfloat16 l1 = __float2bfloat16(oii - __bfloat162float(h1));
    *(__nv_bfloat162*)(oh + off) = __nv_bfloat162(h0, h1);
    *(__nv_bfloat162*)(ol + off) = __nv_bfloat162(l0, l1);
}

// ---------------------------------------------------------------------------
// V transpose+split: xv fp32 [b,s,hkv,128] -> vth/vtl [b,hkv,128,1024]
// grid (S/32, 128/32, B*HKV), block 256
// ---------------------------------------------------------------------------
__global__ void __launch_bounds__(256) transpose_split_v(const float* __restrict__ xv,
                                                         __nv_bfloat16* __restrict__ vth,
                                                         __nv_bfloat16* __restrict__ vtl)
{
    __shared__ float t[32][33];
    const int tid = threadIdx.x;
    const int tx = tid & 31, ty = tid >> 5;
    const int s0 = blockIdx.x * 32, d0 = blockIdx.y * 32;
    const int bh = blockIdx.z;
    const int b = bh >> 3, hk = bh & 7;
    #pragma unroll
    for (int r = 0; r < 4; r++)
        t[ty + r*8][tx] = xv[(size_t)(b*S_ + s0 + ty + r*8)*KVD_ + hk*HD_ + d0 + tx];
    __syncthreads();
    #pragma unroll
    for (int r = 0; r < 4; r++) {
        float v = t[tx][ty + r*8];
        __nv_bfloat16 h = __float2bfloat16(v);
        __nv_bfloat16 l = __float2bfloat16(v - __bfloat162float(h));
        size_t o = ((size_t)bh * HD_ + d0 + ty + r*8) * S_ + s0 + tx;
        vth[o] = h;
        vtl[o] = l;
    }
}

// ---------------------------------------------------------------------------
// Flash attention, bf16 mma.sync with hi/lo splits.
// Grid (S/128, H, B), block 256 (8 warps x 16 q rows).
// smem: Qh(32K) Ql(32K) | 2 stages x [Kh 16K | Kl 16K | Vth 16K | Vtl 16K]
// ---------------------------------------------------------------------------
#define AT_STAGE 65536
#define AT_SMEM  (65536 + 2*AT_STAGE + 128)

__global__ void __launch_bounds__(256, 1) attn_mma(const __nv_bfloat16* __restrict__ qh,
                                                   const __nv_bfloat16* __restrict__ ql,
                                                   const __nv_bfloat16* __restrict__ kh,
                                                   const __nv_bfloat16* __restrict__ kl,
                                                   const __nv_bfloat16* __restrict__ vth,
                                                   const __nv_bfloat16* __restrict__ vtl,
                                                   float* __restrict__ Og)
{
    extern __shared__ char smem[];
    const uint32_t base = (smem_u32(smem) + 127u) & ~127u;
    const int tid  = threadIdx.x;
    const int lane = tid & 31;
    const int w    = tid >> 5;
    const int q0   = blockIdx.x * 128;
    const int h    = blockIdx.y;
    const int b    = blockIdx.z;
    const int hk   = h >> 2;
    const float scale = 0.08838834764831845f;

    // ---- load Q (hi+lo), group 0 ----
    #pragma unroll
    for (int i = 0; i < 8; i++) {
        const int flat = tid + i*256;          // 0..2047
        const int c = flat >> 10;              // d chunk
        const int r = (flat >> 3) & 127;       // q row
        const int u = flat & 7;
        const size_t src = (size_t)(b*S_ + q0 + r)*D_ + h*HD_ + c*64 + u*8;
        const uint32_t dst = base + c*16384 + SW128((uint32_t)(r*128 + u*16));
        CP16(dst, qh + src);
        CP16(dst + 32768, ql + src);
    }
    CP_COMMIT();

    #define LOAD_KV(t) do {                                                        \
        const uint32_t _sb = base + 65536 + ((t) & 1)*AT_STAGE;                    \
        const int _kv0 = (t) * 64;                                                 \
        _Pragma("unroll")                                                          \
        for (int _i = 0; _i < 4; _i++) {                                           \
            const int _f = tid + _i*256;        /* 0..1023 */                      \
            const int _c = _f >> 9;                                                \
            const int _r = (_f >> 3) & 63;                                         \
            const int _u = _f & 7;                                                 \
            const size_t _src = (size_t)(b*S_ + _kv0 + _r)*KVD_ + hk*HD_ + _c*64 + _u*8; \
            const uint32_t _d = _sb + _c*8192 + SW128((uint32_t)(_r*128 + _u*16)); \
            CP16(_d,          kh + _src);                                          \
            CP16(_d + 16384,  kl + _src);                                          \
        }                                                                          \
        _Pragma("unroll")                                                          \
        for (int _i = 0; _i < 4; _i++) {                                           \
            const int _f = tid + _i*256;                                           \
            const int _r = _f >> 3;             /* d row 0..127 */                 \
            const int _u = _f & 7;                                                 \
            const size_t _src = ((size_t)(b*HKV_ + hk)*HD_ + _r)*S_ + _kv0 + _u*8; \
            const uint32_t _d = _sb + 32768 + SW128((uint32_t)(_r*128 + _u*16));   \
            CP16(_d,          vth + _src);                                         \
            CP16(_d + 16384,  vtl + _src);                                         \
        }                                                                          \
        CP_COMMIT();                                                               \
    } while (0)

    LOAD_KV(0);
    LOAD_KV(1);

    float acc_o[16][4];
    #pragma unroll
    for (int t8 = 0; t8 < 16; t8++)
        #pragma unroll
        for (int r = 0; r < 4; r++) acc_o[t8][r] = 0.f;
    float m1 = -INFINITY, m2 = -INFINITY, l1 = 0.f, l2 = 0.f;

    const uint32_t rowA = (uint32_t)((w*16 + (lane & 15)) * 128);

    for (int t = 0; t < S_/64; t++) {
        if (t == S_/64 - 1) asm volatile("cp.async.wait_group 0;" ::: "memory");
        else                asm volatile("cp.async.wait_group 1;" ::: "memory");
        __syncthreads();

        const uint32_t sb = base + 65536 + (t & 1)*AT_STAGE;

        // ---- S = Q K^T (3 bf16 terms), acc fp32 ----
        float sa[8][4];
        #pragma unroll
        for (int t8 = 0; t8 < 8; t8++)
            #pragma unroll
            for (int r = 0; r < 4; r++) sa[t8][r] = 0.f;

        #pragma unroll
        for (int ks = 0; ks < 8; ks++) {
            const int chunk = ks >> 2;
            const uint32_t kb = (uint32_t)((ks & 3)*32 + (lane >> 4)*16);
            uint32_t qah[4], qal[4];
            const uint32_t swA = SW128(rowA + kb);
            LDSM4(qah[0], qah[1], qah[2], qah[3], base + chunk*16384 + swA);
            LDSM4(qal[0], qal[1], qal[2], qal[3], base + 32768 + chunk*16384 + swA);
            #pragma unroll
            for (int nj = 0; nj < 4; nj++) {
                const uint32_t sw = SW128((uint32_t)((nj*16 + (lane & 15))*128) + kb);
                uint32_t k0h[2], k1h[2], k0l[2], k1l[2];
                LDSM4(k0h[0], k1h[0], k0h[1], k1h[1], sb + chunk*8192 + sw);
                LDSM4(k0l[0], k1l[0], k0l[1], k1l[1], sb + 16384 + chunk*8192 + sw);
                MMA_BF16(sa[2*nj],   qah, k0h);
                MMA_BF16(sa[2*nj],   qah, k0l);
                MMA_BF16(sa[2*nj],   qal, k0h);
                MMA_BF16(sa[2*nj+1], qah, k1h);
                MMA_BF16(sa[2*nj+1], qah, k1l);
                MMA_BF16(sa[2*nj+1], qal, k1h);
            }
        }

        // ---- online softmax on fragments ----
        float mx1 = -INFINITY, mx2 = -INFINITY;
        #pragma unroll
        for (int t8 = 0; t8 < 8; t8++) {
            mx1 = fmaxf(mx1, fmaxf(sa[t8][0], sa[t8][1]));
            mx2 = fmaxf(mx2, fmaxf(sa[t8][2], sa[t8][3]));
        }
        mx1 *= scale; mx2 *= scale;
        mx1 = fmaxf(mx1, __shfl_xor_sync(0xFFFFFFFFu, mx1, 1));
        mx1 = fmaxf(mx1, __shfl_xor_sync(0xFFFFFFFFu, mx1, 2));
        mx2 = fmaxf(mx2, __shfl_xor_sync(0xFFFFFFFFu, mx2, 1));
        mx2 = fmaxf(mx2, __shfl_xor_sync(0xFFFFFFFFu, mx2, 2));
        const float mn1 = fmaxf(m1, mx1), mn2 = fmaxf(m2, mx2);
        const float al1 = __expf(m1 - mn1), al2 = __expf(m2 - mn2);

        uint32_t Ph[4][4], Pl[4][4];
        float sum1 = 0.f, sum2 = 0.f;
        #pragma unroll
        for (int t8 = 0; t8 < 8; t8++) {
            const float p0 = __expf(sa[t8][0]*scale - mn1);
            const float p1 = __expf(sa[t8][1]*scale - mn1);
            const float p2 = __expf(sa[t8][2]*scale - mn2);
            const float p3 = __expf(sa[t8][3]*scale - mn2);
            sum1 += p0 + p1; sum2 += p2 + p3;
            __nv_bfloat162 h01 = __floats2bfloat162_rn(p0, p1);
            __nv_bfloat162 h23 = __floats2bfloat162_rn(p2, p3);
            __nv_bfloat162 l01 = __floats2bfloat162_rn(p0 - __bfloat162float(h01.x),
                                                       p1 - __bfloat162float(h01.y));
            __nv_bfloat162 l23 = __floats2bfloat162_rn(p2 - __bfloat162float(h23.x),
                                                       p3 - __bfloat162float(h23.y));
            const int j = t8 >> 1;
            const int o = (t8 & 1) ? 2 : 0;
            Ph[j][o]     = *(uint32_t*)&h01;
            Ph[j][o + 1] = *(uint32_t*)&h23;
            Pl[j][o]     = *(uint32_t*)&l01;
            Pl[j][o + 1] = *(uint32_t*)&l23;
        }
        sum1 += __shfl_xor_sync(0xFFFFFFFFu, sum1, 1);
        sum1 += __shfl_xor_sync(0xFFFFFFFFu, sum1, 2);
        sum2 += __shfl_xor_sync(0xFFFFFFFFu, sum2, 1);
        sum2 += __shfl_xor_sync(0xFFFFFFFFu, sum2, 2);
        l1 = l1*al1 + sum1;  m1 = mn1;
        l2 = l2*al2 + sum2;  m2 = mn2;

        #pragma unroll
        for (int t8 = 0; t8 < 16; t8++) {
            acc_o[t8][0] *= al1; acc_o[t8][1] *= al1;
            acc_o[t8][2] *= al2; acc_o[t8][3] *= al2;
        }

        // ---- O += P V (3 terms); Vt stored [d rows][kv cols] ----
        #pragma unroll
        for (int j = 0; j < 4; j++) {
            const uint32_t kb = (uint32_t)(j*32 + (lane >> 4)*16);
            #pragma unroll
            for (int nj = 0; nj < 8; nj++) {
                const uint32_t sw = SW128((uint32_t)((nj*16 + (lane & 15))*128) + kb);
                uint32_t v0h[2], v1h[2], v0l[2], v1l[2];
                LDSM4(v0h[0], v1h[0], v0h[1], v1h[1], sb + 32768 + sw);
                LDSM4(v0l[0], v1l[0], v0l[1], v1l[1], sb + 49152 + sw);
                MMA_BF16(acc_o[2*nj],   Ph[j], v0h);
                MMA_BF16(acc_o[2*nj],   Ph[j], v0l);
                MMA_BF16(acc_o[2*nj],   Pl[j], v0h);
                MMA_BF16(acc_o[2*nj+1], Ph[j], v1h);
                MMA_BF16(acc_o[2*nj+1], Ph[j], v1l);
                MMA_BF16(acc_o[2*nj+1], Pl[j], v1h);
            }
        }

        __syncthreads();                 // stage free before overwrite
        if (t + 2 < S_/64) LOAD_KV(t + 2);
    }

    const float inv1 = 1.f / l1, inv2 = 1.f / l2;
    const int r1 = q0 + w*16 + (lane >> 2);
    #pragma unroll
    for (int t8 = 0; t8 < 16; t8++) {
        const int c = h*HD_ + t8*8 + (lane & 3)*2;
        *(float2*)(Og + (size_t)(b*S_ + r1)*D_ + c) =
            make_float2(acc_o[t8][0]*inv1, acc_o[t8][1]*inv1);
        *(float2*)(Og + (size_t)(b*S_ + r1 + 8)*D_ + c) =
            make_float2(acc_o[t8][2]*inv2, acc_o[t8][3]*inv2);
    }
    #undef LOAD_KV
}

// ---------------------------------------------------------------------------
// Launch
// ---------------------------------------------------------------------------
extern "C" void kernel_launch(void* const* d_in, const int* in_sizes, int n_in,
                              void* d_out, int out_size)
{
    const float* x  = (const float*)d_in[0];
    const float* fc = (const float*)d_in[1];
    const float* fs = (const float*)d_in[2];
    const float* wq = (const float*)d_in[3];
    const float* wk = (const float*)d_in[4];
    const float* wv = (const float*)d_in[5];
    const float* wo = (const float*)d_in[6];
    float* out = (float*)d_out;

    float *xq, *xk, *xv, *attn;
    cudaGetSymbolAddress((void**)&xq,   g_xq);
    cudaGetSymbolAddress((void**)&xk,   g_xk);
    cudaGetSymbolAddress((void**)&xv,   g_xv);
    cudaGetSymbolAddress((void**)&attn, g_attn);
    __nv_bfloat16 *ah, *al, *kh, *kl, *vth, *vtl;
    __nv_bfloat16 *wqh, *wql, *wkh, *wkl, *wvh, *wvl, *woh, *wol;
    cudaGetSymbolAddress((void**)&ah,  g_ah);
    cudaGetSymbolAddress((void**)&al,  g_al);
    cudaGetSymbolAddress((void**)&kh,  g_kh);
    cudaGetSymbolAddress((void**)&kl,  g_kl);
    cudaGetSymbolAddress((void**)&vth, g_vth);
    cudaGetSymbolAddress((void**)&vtl, g_vtl);
    cudaGetSymbolAddress((void**)&wqh, g_wqh);
    cudaGetSymbolAddress((void**)&wql, g_wql);
    cudaGetSymbolAddress((void**)&wkh, g_wkh);
    cudaGetSymbolAddress((void**)&wkl, g_wkl);
    cudaGetSymbolAddress((void**)&wvh, g_wvh);
    cudaGetSymbolAddress((void**)&wvl, g_wvl);
    cudaGetSymbolAddress((void**)&woh, g_woh);
    cudaGetSymbolAddress((void**)&wol, g_wol);

    cudaFuncSetAttribute(gemm_tc,  cudaFuncAttributeMaxDynamicSharedMemorySize, GEMM_SMEM);
    cudaFuncSetAttribute(attn_mma, cudaFuncAttributeMaxDynamicSharedMemorySize, AT_SMEM);

    // 1) conversions
    split_fp32<<<(M_*D_/4 + 255)/256, 256>>>(x, ah, al, M_*D_);
    transpose_split<<<dim3(D_/32,   D_/32), 256>>>(wq, wqh, wql, D_, D_);
    transpose_split<<<dim3(KVD_/32, D_/32), 256>>>(wk, wkh, wkl, D_, KVD_);
    transpose_split<<<dim3(KVD_/32, D_/32), 256>>>(wv, wvh, wvl, D_, KVD_);
    transpose_split<<<dim3(D_/32,   D_/32), 256>>>(wo, woh, wol, D_, D_);

    // 2) QKV projections
    gemm_tc<<<dim3(D_/128,   M_/128), 256, GEMM_SMEM>>>(ah, al, wqh, wql, xq, D_,   D_);
    gemm_tc<<<dim3(KVD_/128, M_/128), 256, GEMM_SMEM>>>(ah, al, wkh, wkl, xk, KVD_, D_);
    gemm_tc<<<dim3(KVD_/128, M_/128), 256, GEMM_SMEM>>>(ah, al, wvh, wvl, xv, KVD_, D_);

    // 3) RoPE + split (Q reuses ah/al), V transpose+split
    {
        int totq = B_ * S_ * H_   * (HD_ / 2);
        int totk = B_ * S_ * HKV_ * (HD_ / 2);
        rope_split<<<(totq + 255)/256, 256>>>(xq, fc, fs, ah, al, H_,   totq);
        rope_split<<<(totk + 255)/256, 256>>>(xk, fc, fs, kh, kl, HKV_, totk);
        transpose_split_v<<<dim3(S_/32, HD_/32, B_*HKV_), 256>>>(xv, vth, vtl);
    }

    // 4) attention (tensor-core flash)
    attn_mma<<<dim3(S_/128, H_, B_), 256, AT_SMEM>>>(ah, al, kh, kl, vth, vtl, attn);

    // 5) output projection
    split_fp32<<<(M_*D_/4 + 255)/256, 256>>>(attn, ah, al, M_*D_);
    gemm_tc<<<dim3(D_/128, M_/128), 256, GEMM_SMEM>>>(ah, al, woh, wol, out, D_, D_);
}